// round 6
// baseline (speedup 1.0000x reference)
#include <cuda_runtime.h>

// Shapes fixed by the problem
#define B_  32
#define Q_  900
#define C_  91
#define T_  30
#define BQ  (B_ * Q_)                 // 28800
#define CSZ ((size_t)B_ * Q_ * Q_)    // 25,920,000
#define NR4 (Q_ / 4)                  // 225 float4 per row
#define ROWS_PER_BLK 8
#define BLKS_PER_BATCH ((Q_ + ROWS_PER_BLK - 1) / ROWS_PER_BLK)   // 113

// Scratch (device globals — zero-initialized at module load; no allocation)
__device__ int g_cnt[B_];      // valid pseudo-target count per batch
__device__ int g_done[B_];     // per-batch completion ticket (self-resetting)
__device__ int g_vjl[BQ];      // per batch: packed (j | label<<16), compacted

// ---------------------------------------------------------------------------
__device__ __forceinline__ float fast_rcp(float x) {
    float y = __int_as_float(0x7EF311C3 - __float_as_int(x));
    y = y * fmaf(-x, y, 2.0f);
    y = y * fmaf(-x, y, 2.0f);
    return y;
}

__device__ __forceinline__ float4 to_xyxy(float4 b) {
    float hw = 0.5f * b.z, hh = 0.5f * b.w;
    return make_float4(b.x - hw, b.y - hh, b.x + hw, b.y + hh);
}

// Precise GIoU (IEEE div) — the filter comparison is boundary-sensitive; must
// match reference rounding op-for-op.
__device__ __forceinline__ float giou_precise(float4 xa, float aa, float4 xb, float ab) {
    float w = fmaxf(fminf(xa.z, xb.z) - fmaxf(xa.x, xb.x), 0.0f);
    float h = fmaxf(fminf(xa.w, xb.w) - fmaxf(xa.y, xb.y), 0.0f);
    float inter = w * h;
    float uni = aa + ab - inter;
    float wc = fmaxf(fmaxf(xa.z, xb.z) - fminf(xa.x, xb.x), 0.0f);
    float hc = fmaxf(fmaxf(xa.w, xb.w) - fminf(xa.y, xb.y), 0.0f);
    float ac = wc * hc;
    return inter / uni - (ac - uni) / ac;
}

// Fast GIoU for cost entries (values, not comparisons): fused single reciprocal.
__device__ __forceinline__ float giou_fast(float4 xa, float aa, float4 xb, float ab) {
    float w = fmaxf(fminf(xa.z, xb.z) - fmaxf(xa.x, xb.x), 0.0f);
    float h = fmaxf(fminf(xa.w, xb.w) - fmaxf(xa.y, xb.y), 0.0f);
    float inter = w * h;
    float uni = aa + ab - inter;
    float wc = fmaxf(xa.z, xb.z) - fminf(xa.x, xb.x);
    float hc = fmaxf(xa.w, xb.w) - fminf(xa.y, xb.y);
    float ac = wc * hc;
    float num = inter * ac - (ac - uni) * uni;
    return num * fast_rcp(uni * ac);
}

__device__ __forceinline__ unsigned ordkey(float v) {
    unsigned u = __float_as_uint(v);
    return ((int)u >= 0) ? (u | 0x80000000u) : ~u;
}

// ---------------------------------------------------------------------------
// K1: pseudo-label generation + compaction. One warp per (b, j).
// ---------------------------------------------------------------------------
__global__ __launch_bounds__(256) void pseudo_kernel(
    const float*  __restrict__ logits_base,
    const float4* __restrict__ boxes_base,
    const float4* __restrict__ targets,
    float* __restrict__ out, int write_mask)
{
    int w    = (blockIdx.x * 256 + threadIdx.x) >> 5;   // exactly covers BQ
    int lane = threadIdx.x & 31;
    int b    = w / Q_;

    const float* lg = logits_base + (size_t)w * C_;
    float v0 = lg[lane];
    float v1 = lg[lane + 32];
    float v2 = (lane + 64 < C_) ? lg[lane + 64] : -3.4e38f;
    unsigned k0 = ordkey(v0), k1 = ordkey(v1), k2 = ordkey(v2);
    unsigned best = __reduce_max_sync(0xffffffffu, max(k0, max(k1, k2)));

    int bi;
    unsigned m0 = __ballot_sync(0xffffffffu, k0 == best);
    unsigned m1 = __ballot_sync(0xffffffffu, k1 == best);
    unsigned m2 = __ballot_sync(0xffffffffu, k2 == best);
    if (m0)      bi = __ffs(m0) - 1;
    else if (m1) bi = 32 + __ffs(m1) - 1;
    else         bi = 64 + __ffs(m2) - 1;

    bool keep_prob = best > 0x80000000u;   // max logit > 0 <=> sigmoid > 0.5

    float4 bb = boxes_base[w];
    float4 xb = to_xyxy(bb);
    float  ab = (xb.z - xb.x) * (xb.w - xb.y);

    bool ok = true;
    if (lane < T_) {
        float4 tb = targets[b * T_ + lane];
        float4 xt = to_xyxy(tb);
        float  at = (xt.z - xt.x) * (xt.w - xt.y);
        float  g  = giou_precise(xb, ab, xt, at);
        ok = ((-g) > -0.1f);
    }
    bool all_ok = __all_sync(0xffffffffu, ok);

    if (lane == 0) {
        bool m = keep_prob && all_ok;
        if (write_mask) out[CSZ + w] = m ? 1.0f : 0.0f;
        if (m) {
            int slot = atomicAdd(&g_cnt[b], 1);
            g_vjl[b * Q_ + slot] = (w - b * Q_) | (bi << 16);
        }
    }
}

// ---------------------------------------------------------------------------
// K2: single-pass cost tile. Block owns 8 rows of batch b.
//   Phase A: build the 8x900 tile in smem (1e9 fill + valid-column compute).
//   Phase B: stream smem -> global with coalesced float4 stores (one pass).
//   Tail: last block per batch resets g_cnt/g_done (replaces zero_kernel).
// ---------------------------------------------------------------------------
__global__ __launch_bounds__(256) void cost_kernel(
    const float*  __restrict__ logits,       // current pred logits [B,Q,C]
    const float4* __restrict__ boxes,        // current pred boxes
    const float4* __restrict__ boxes_base,   // pseudo-target boxes
    float* __restrict__ out)
{
    __shared__ float sval[ROWS_PER_BLK * Q_];    // 28.8 KB
    __shared__ float4 sbx[ROWS_PER_BLK];         // xyxy of the 8 i-boxes
    __shared__ float4 sbb[ROWS_PER_BLK];         // cxcywh of the 8 i-boxes
    __shared__ float  sba[ROWS_PER_BLK];

    int b  = blockIdx.y;
    int i0 = blockIdx.x * ROWS_PER_BLK;
    int t  = threadIdx.x;
    int nrows = min(ROWS_PER_BLK, Q_ - i0);

    // ---- phase A0: smem fill with 1e9 + stage i-boxes ----
    float4* sval4 = (float4*)sval;
    const float4 F = make_float4(1e9f, 1e9f, 1e9f, 1e9f);
    #pragma unroll
    for (int k = 0; k < (ROWS_PER_BLK * NR4 + 255) / 256; ++k) {
        int idx = k * 256 + t;
        if (idx < ROWS_PER_BLK * NR4) sval4[idx] = F;
    }
    if (t < nrows) {
        float4 bi = boxes[b * Q_ + i0 + t];
        float4 xi = to_xyxy(bi);
        sbb[t] = bi;
        sbx[t] = xi;
        sba[t] = (xi.z - xi.x) * (xi.w - xi.y);
    }
    __syncthreads();

    // ---- phase A1: compute valid columns into smem ----
    int n = g_cnt[b];
    int total = nrows * n;
    for (int idx = t; idx < total; idx += 256) {
        int ii = idx / n;
        int v  = idx - ii * n;

        int jl  = g_vjl[b * Q_ + v];
        int j   = jl & 0xFFFF;
        int lab = jl >> 16;

        float4 bi = sbb[ii];
        float4 xi = sbx[ii];
        float  ai = sba[ii];

        float4 bj = boxes_base[b * Q_ + j];
        float4 xj = to_xyxy(bj);
        float  aj = (xj.z - xj.x) * (xj.w - xj.y);

        float x   = logits[((size_t)b * Q_ + i0 + ii) * C_ + lab];
        float p   = fast_rcp(1.0f + __expf(-x));
        float omp = 1.0f - p;
        float pos = 0.25f * omp * omp * (-__logf(p   + 1e-8f));
        float neg = 0.75f * p   * p   * (-__logf(omp + 1e-8f));
        float cls = 2.0f * (pos - neg);

        float l1 = fabsf(bi.x - bj.x) + fabsf(bi.y - bj.y)
                 + fabsf(bi.z - bj.z) + fabsf(bi.w - bj.w);
        float g  = giou_fast(xi, ai, xj, aj);

        sval[ii * Q_ + j] = fmaf(5.0f, l1, cls) - 2.0f * g;
    }
    __syncthreads();

    // ---- phase B: coalesced float4 stores to global (single pass) ----
    float4* out4 = (float4*)out;
    size_t  obase = ((size_t)b * Q_ + i0) * NR4;
    #pragma unroll
    for (int k = 0; k < (ROWS_PER_BLK * NR4 + 255) / 256; ++k) {
        int idx = k * 256 + t;
        if (idx < nrows * NR4)
            out4[obase + idx] = sval4[idx];
    }

    // ---- tail: last block of this batch resets counters for next replay ----
    __threadfence();
    if (t == 0) {
        int d = atomicAdd(&g_done[b], 1);
        if (d == BLKS_PER_BATCH - 1) {
            g_cnt[b]  = 0;
            g_done[b] = 0;
        }
    }
}

// ---------------------------------------------------------------------------
extern "C" void kernel_launch(void* const* d_in, const int* in_sizes, int n_in,
                              void* d_out, int out_size)
{
    const float*  pred_logits      = (const float*) d_in[0];
    const float4* pred_boxes       = (const float4*)d_in[1];
    const float*  pred_logits_base = (const float*) d_in[2];
    const float4* pred_boxes_base  = (const float4*)d_in[3];
    const float4* targets_boxes    = (const float4*)d_in[4];
    float* out = (float*)d_out;

    int write_mask = (out_size >= (int)(CSZ + BQ)) ? 1 : 0;

    pseudo_kernel<<<BQ / 8, 256>>>(pred_logits_base, pred_boxes_base,
                                   targets_boxes, out, write_mask);

    dim3 grid(BLKS_PER_BATCH, B_);   // (113, 32)
    cost_kernel<<<grid, 256>>>(pred_logits, pred_boxes, pred_boxes_base, out);
}

// round 7
// speedup vs baseline: 1.0083x; 1.0083x over previous
#include <cuda_runtime.h>

// Shapes fixed by the problem
#define B_  32
#define Q_  900
#define C_  91
#define T_  30
#define BQ  (B_ * Q_)                 // 28800
#define CSZ ((size_t)B_ * Q_ * Q_)    // 25,920,000
#define NR4 (Q_ / 4)                  // 225 float4 per row
#define ROWS_PER_BLK 8
#define BLKS_PER_BATCH ((Q_ + ROWS_PER_BLK - 1) / ROWS_PER_BLK)   // 113

// Scratch (device globals — zero-initialized at module load; no allocation)
__device__ int g_cnt[B_];      // valid pseudo-target count per batch
__device__ int g_done[B_];     // per-batch completion ticket (self-resetting)
__device__ int g_vjl[BQ];      // per batch: packed (j | label<<16), compacted

// ---------------------------------------------------------------------------
// FMA-pipe math (no MUFU). Computed cost entries have large accuracy slack
// (norm-based rel_err dominated by the exact 1e9 fill).
// ---------------------------------------------------------------------------
__device__ __forceinline__ float fast_rcp(float x) {
    float y = __int_as_float(0x7EF311C3 - __float_as_int(x));
    y = y * fmaf(-x, y, 2.0f);
    y = y * fmaf(-x, y, 2.0f);
    return y;
}

// exp(x) = 2^(x*log2e), degree-5 poly on f in [-0.5,0.5] + exponent add.
__device__ __forceinline__ float fast_exp(float x) {
    float y = fminf(fmaxf(x * 1.4426950408889634f, -120.0f), 120.0f);
    float n = rintf(y);
    float f = y - n;
    float p = 1.3333558146e-3f;
    p = fmaf(p, f, 9.6180905e-3f);
    p = fmaf(p, f, 5.550410866e-2f);
    p = fmaf(p, f, 2.402265069e-1f);
    p = fmaf(p, f, 6.931471806e-1f);
    p = fmaf(p, f, 1.0f);
    return __int_as_float(__float_as_int(p) + (((int)n) << 23));
}

// ln(x) for x > 0 (Cephes-style), err ~1e-7.
__device__ __forceinline__ float fast_log(float x) {
    int   xi = __float_as_int(x);
    int   e  = (xi >> 23) - 127;
    float m  = __int_as_float((xi & 0x007FFFFF) | 0x3F800000);  // [1,2)
    bool  c  = m > 1.41421356f;
    m = c ? 0.5f * m : m;
    e = c ? e + 1 : e;
    float f = m - 1.0f;
    float w = f * f;
    float p = 7.0376836292e-2f;
    p = fmaf(p, f, -1.1514610310e-1f);
    p = fmaf(p, f,  1.1676998740e-1f);
    p = fmaf(p, f, -1.2420140846e-1f);
    p = fmaf(p, f,  1.4249322787e-1f);
    p = fmaf(p, f, -1.6668057665e-1f);
    p = fmaf(p, f,  2.0000714765e-1f);
    p = fmaf(p, f, -2.4999993993e-1f);
    p = fmaf(p, f,  3.3333331174e-1f);
    float y = f * w * p - 0.5f * w;
    return fmaf((float)e, 0.69314718056f, f + y);
}

__device__ __forceinline__ float4 to_xyxy(float4 b) {
    float hw = 0.5f * b.z, hh = 0.5f * b.w;
    return make_float4(b.x - hw, b.y - hh, b.x + hw, b.y + hh);
}

// Precise GIoU (IEEE div) — only for the boundary-sensitive filter compare.
__device__ __forceinline__ float giou_precise(float4 xa, float aa, float4 xb, float ab) {
    float w = fmaxf(fminf(xa.z, xb.z) - fmaxf(xa.x, xb.x), 0.0f);
    float h = fmaxf(fminf(xa.w, xb.w) - fmaxf(xa.y, xb.y), 0.0f);
    float inter = w * h;
    float uni = aa + ab - inter;
    float wc = fmaxf(fmaxf(xa.z, xb.z) - fminf(xa.x, xb.x), 0.0f);
    float hc = fmaxf(fmaxf(xa.w, xb.w) - fminf(xa.y, xb.y), 0.0f);
    float ac = wc * hc;
    return inter / uni - (ac - uni) / ac;
}

// Fast GIoU for cost values: one fused Newton reciprocal.
__device__ __forceinline__ float giou_fast(float4 xa, float aa, float4 xb, float ab) {
    float w = fmaxf(fminf(xa.z, xb.z) - fmaxf(xa.x, xb.x), 0.0f);
    float h = fmaxf(fminf(xa.w, xb.w) - fmaxf(xa.y, xb.y), 0.0f);
    float inter = w * h;
    float uni = aa + ab - inter;
    float wc = fmaxf(xa.z, xb.z) - fminf(xa.x, xb.x);
    float hc = fmaxf(xa.w, xb.w) - fminf(xa.y, xb.y);
    float ac = wc * hc;
    float num = inter * ac - (ac - uni) * uni;
    return num * fast_rcp(uni * ac);
}

__device__ __forceinline__ unsigned ordkey(float v) {
    unsigned u = __float_as_uint(v);
    return ((int)u >= 0) ? (u | 0x80000000u) : ~u;
}

// ---------------------------------------------------------------------------
// K1: pseudo-label generation + compaction. One warp per (b, j).
// ---------------------------------------------------------------------------
__global__ __launch_bounds__(256) void pseudo_kernel(
    const float*  __restrict__ logits_base,
    const float4* __restrict__ boxes_base,
    const float4* __restrict__ targets,
    float* __restrict__ out, int write_mask)
{
    int w    = (blockIdx.x * 256 + threadIdx.x) >> 5;   // exactly covers BQ
    int lane = threadIdx.x & 31;
    int b    = w / Q_;

    const float* lg = logits_base + (size_t)w * C_;
    float v0 = lg[lane];
    float v1 = lg[lane + 32];
    float v2 = (lane + 64 < C_) ? lg[lane + 64] : -3.4e38f;
    unsigned k0 = ordkey(v0), k1 = ordkey(v1), k2 = ordkey(v2);
    unsigned best = __reduce_max_sync(0xffffffffu, max(k0, max(k1, k2)));

    int bi;
    unsigned m0 = __ballot_sync(0xffffffffu, k0 == best);
    unsigned m1 = __ballot_sync(0xffffffffu, k1 == best);
    unsigned m2 = __ballot_sync(0xffffffffu, k2 == best);
    if (m0)      bi = __ffs(m0) - 1;
    else if (m1) bi = 32 + __ffs(m1) - 1;
    else         bi = 64 + __ffs(m2) - 1;

    bool keep_prob = best > 0x80000000u;   // max logit > 0 <=> sigmoid > 0.5

    float4 bb = boxes_base[w];
    float4 xb = to_xyxy(bb);
    float  ab = (xb.z - xb.x) * (xb.w - xb.y);

    bool ok = true;
    if (lane < T_) {
        float4 tb = targets[b * T_ + lane];
        float4 xt = to_xyxy(tb);
        float  at = (xt.z - xt.x) * (xt.w - xt.y);
        float  g  = giou_precise(xb, ab, xt, at);
        ok = ((-g) > -0.1f);
    }
    bool all_ok = __all_sync(0xffffffffu, ok);

    if (lane == 0) {
        bool m = keep_prob && all_ok;
        if (write_mask) out[CSZ + w] = m ? 1.0f : 0.0f;
        if (m) {
            int slot = atomicAdd(&g_cnt[b], 1);
            g_vjl[b * Q_ + slot] = (w - b * Q_) | (bi << 16);
        }
    }
}

// ---------------------------------------------------------------------------
// K2: fill + overwrite. Block owns 8 rows of batch b.
//   Phase 1: dense float4 fill with 1e9 (lines stay in L2 between phases).
//   Phase 2: compute valid columns (FMA-pipe math only) and overwrite.
//   Tail: last block per batch resets counters (replaces zero_kernel).
// ---------------------------------------------------------------------------
__global__ __launch_bounds__(256) void cost_kernel(
    const float*  __restrict__ logits,       // current pred logits [B,Q,C]
    const float4* __restrict__ boxes,        // current pred boxes
    const float4* __restrict__ boxes_base,   // pseudo-target boxes
    float* __restrict__ out)
{
    int b  = blockIdx.y;
    int i0 = blockIdx.x * ROWS_PER_BLK;
    int t  = threadIdx.x;
    int nrows = min(ROWS_PER_BLK, Q_ - i0);

    // ---- phase 1: dense fill ----
    float4* out4 = (float4*)out;
    const float4 F = make_float4(1e9f, 1e9f, 1e9f, 1e9f);
    size_t obase4 = ((size_t)b * Q_ + i0) * NR4;
    #pragma unroll
    for (int k = 0; k < (ROWS_PER_BLK * NR4 + 255) / 256; ++k) {
        int idx = k * 256 + t;
        if (idx < nrows * NR4)
            out4[obase4 + idx] = F;
    }
    __syncthreads();   // order phase-1 writes before phase-2 overwrites (CTA fence)

    // ---- phase 2: compute valid columns only (no MUFU) ----
    int n = g_cnt[b];
    int total = nrows * n;
    for (int idx = t; idx < total; idx += 256) {
        int ii = idx / n;
        int v  = idx - ii * n;
        int i  = i0 + ii;

        int jl  = g_vjl[b * Q_ + v];
        int j   = jl & 0xFFFF;
        int lab = jl >> 16;

        float4 bi = boxes[b * Q_ + i];
        float4 xi = to_xyxy(bi);
        float  ai = (xi.z - xi.x) * (xi.w - xi.y);

        float4 bj = boxes_base[b * Q_ + j];
        float4 xj = to_xyxy(bj);
        float  aj = (xj.z - xj.x) * (xj.w - xj.y);

        // focal class cost at label lab, weighted by W_CLASS=2
        float x   = logits[((size_t)b * Q_ + i) * C_ + lab];
        float p   = fast_rcp(1.0f + fast_exp(-x));
        float omp = 1.0f - p;
        float pos = 0.25f * omp * omp * (-fast_log(p   + 1e-8f));
        float neg = 0.75f * p   * p   * (-fast_log(omp + 1e-8f));
        float cls = 2.0f * (pos - neg);

        float l1 = fabsf(bi.x - bj.x) + fabsf(bi.y - bj.y)
                 + fabsf(bi.z - bj.z) + fabsf(bi.w - bj.w);
        float g  = giou_fast(xi, ai, xj, aj);

        out[((size_t)b * Q_ + i) * Q_ + j] = fmaf(5.0f, l1, cls) - 2.0f * g;
    }

    // ---- tail: last block of this batch resets counters for next replay ----
    __threadfence();
    if (t == 0) {
        int d = atomicAdd(&g_done[b], 1);
        if (d == BLKS_PER_BATCH - 1) {
            g_cnt[b]  = 0;
            g_done[b] = 0;
        }
    }
}

// ---------------------------------------------------------------------------
extern "C" void kernel_launch(void* const* d_in, const int* in_sizes, int n_in,
                              void* d_out, int out_size)
{
    const float*  pred_logits      = (const float*) d_in[0];
    const float4* pred_boxes       = (const float4*)d_in[1];
    const float*  pred_logits_base = (const float*) d_in[2];
    const float4* pred_boxes_base  = (const float4*)d_in[3];
    const float4* targets_boxes    = (const float4*)d_in[4];
    float* out = (float*)d_out;

    int write_mask = (out_size >= (int)(CSZ + BQ)) ? 1 : 0;

    pseudo_kernel<<<BQ / 8, 256>>>(pred_logits_base, pred_boxes_base,
                                   targets_boxes, out, write_mask);

    dim3 grid(BLKS_PER_BATCH, B_);   // (113, 32)
    cost_kernel<<<grid, 256>>>(pred_logits, pred_boxes, pred_boxes_base, out);
}

// round 8
// speedup vs baseline: 1.1058x; 1.0968x over previous
#include <cuda_runtime.h>

// Shapes fixed by the problem
#define B_  32
#define Q_  900
#define C_  91
#define T_  30
#define BQ  (B_ * Q_)                 // 28800
#define CSZ ((size_t)B_ * Q_ * Q_)    // 25,920,000
#define NR4 (Q_ / 4)                  // 225 float4 per row
#define ROWS_PER_BLK 8
#define BLKS_PER_BATCH ((Q_ + ROWS_PER_BLK - 1) / ROWS_PER_BLK)   // 113

// Scratch (device globals — fully rewritten every launch; no allocation)
__device__ unsigned char g_mask[BQ];
__device__ short         g_label[BQ];

// ---------------------------------------------------------------------------
// FMA-pipe math (no MUFU) for cost values; filter path stays IEEE-precise.
// ---------------------------------------------------------------------------
__device__ __forceinline__ float fast_rcp(float x) {
    float y = __int_as_float(0x7EF311C3 - __float_as_int(x));
    y = y * fmaf(-x, y, 2.0f);
    y = y * fmaf(-x, y, 2.0f);
    return y;
}

__device__ __forceinline__ float fast_exp(float x) {
    float y = fminf(fmaxf(x * 1.4426950408889634f, -120.0f), 120.0f);
    float n = rintf(y);
    float f = y - n;
    float p = 1.3333558146e-3f;
    p = fmaf(p, f, 9.6180905e-3f);
    p = fmaf(p, f, 5.550410866e-2f);
    p = fmaf(p, f, 2.402265069e-1f);
    p = fmaf(p, f, 6.931471806e-1f);
    p = fmaf(p, f, 1.0f);
    return __int_as_float(__float_as_int(p) + (((int)n) << 23));
}

__device__ __forceinline__ float fast_log(float x) {
    int   xi = __float_as_int(x);
    int   e  = (xi >> 23) - 127;
    float m  = __int_as_float((xi & 0x007FFFFF) | 0x3F800000);  // [1,2)
    bool  c  = m > 1.41421356f;
    m = c ? 0.5f * m : m;
    e = c ? e + 1 : e;
    float f = m - 1.0f;
    float w = f * f;
    float p = 7.0376836292e-2f;
    p = fmaf(p, f, -1.1514610310e-1f);
    p = fmaf(p, f,  1.1676998740e-1f);
    p = fmaf(p, f, -1.2420140846e-1f);
    p = fmaf(p, f,  1.4249322787e-1f);
    p = fmaf(p, f, -1.6668057665e-1f);
    p = fmaf(p, f,  2.0000714765e-1f);
    p = fmaf(p, f, -2.4999993993e-1f);
    p = fmaf(p, f,  3.3333331174e-1f);
    float y = f * w * p - 0.5f * w;
    return fmaf((float)e, 0.69314718056f, f + y);
}

__device__ __forceinline__ float4 to_xyxy(float4 b) {
    float hw = 0.5f * b.z, hh = 0.5f * b.w;
    return make_float4(b.x - hw, b.y - hh, b.x + hw, b.y + hh);
}

// Precise GIoU (IEEE div) — only for the boundary-sensitive filter compare.
__device__ __forceinline__ float giou_precise(float4 xa, float aa, float4 xb, float ab) {
    float w = fmaxf(fminf(xa.z, xb.z) - fmaxf(xa.x, xb.x), 0.0f);
    float h = fmaxf(fminf(xa.w, xb.w) - fmaxf(xa.y, xb.y), 0.0f);
    float inter = w * h;
    float uni = aa + ab - inter;
    float wc = fmaxf(fmaxf(xa.z, xb.z) - fminf(xa.x, xb.x), 0.0f);
    float hc = fmaxf(fmaxf(xa.w, xb.w) - fminf(xa.y, xb.y), 0.0f);
    float ac = wc * hc;
    return inter / uni - (ac - uni) / ac;
}

// Fast GIoU for cost values: one fused Newton reciprocal.
__device__ __forceinline__ float giou_fast(float4 xa, float aa, float4 xb, float ab) {
    float w = fmaxf(fminf(xa.z, xb.z) - fmaxf(xa.x, xb.x), 0.0f);
    float h = fmaxf(fminf(xa.w, xb.w) - fmaxf(xa.y, xb.y), 0.0f);
    float inter = w * h;
    float uni = aa + ab - inter;
    float wc = fmaxf(xa.z, xb.z) - fminf(xa.x, xb.x);
    float hc = fmaxf(xa.w, xb.w) - fminf(xa.y, xb.y);
    float ac = wc * hc;
    float num = inter * ac - (ac - uni) * uni;
    return num * fast_rcp(uni * ac);
}

__device__ __forceinline__ unsigned ordkey(float v) {
    unsigned u = __float_as_uint(v);
    return ((int)u >= 0) ? (u | 0x80000000u) : ~u;
}

// ---------------------------------------------------------------------------
// K1: pseudo-label generation. One warp per (b, j). Plain stores, no atomics.
// ---------------------------------------------------------------------------
__global__ __launch_bounds__(256) void pseudo_kernel(
    const float*  __restrict__ logits_base,
    const float4* __restrict__ boxes_base,
    const float4* __restrict__ targets,
    float* __restrict__ out, int write_mask)
{
    int w    = (blockIdx.x * 256 + threadIdx.x) >> 5;   // exactly covers BQ
    int lane = threadIdx.x & 31;
    int b    = w / Q_;

    const float* lg = logits_base + (size_t)w * C_;
    float v0 = lg[lane];
    float v1 = lg[lane + 32];
    float v2 = (lane + 64 < C_) ? lg[lane + 64] : -3.4e38f;
    unsigned k0 = ordkey(v0), k1 = ordkey(v1), k2 = ordkey(v2);
    unsigned best = __reduce_max_sync(0xffffffffu, max(k0, max(k1, k2)));

    int bi;
    unsigned m0 = __ballot_sync(0xffffffffu, k0 == best);
    unsigned m1 = __ballot_sync(0xffffffffu, k1 == best);
    unsigned m2 = __ballot_sync(0xffffffffu, k2 == best);
    if (m0)      bi = __ffs(m0) - 1;
    else if (m1) bi = 32 + __ffs(m1) - 1;
    else         bi = 64 + __ffs(m2) - 1;

    bool keep_prob = best > 0x80000000u;   // max logit > 0 <=> sigmoid > 0.5

    float4 bb = boxes_base[w];
    float4 xb = to_xyxy(bb);
    float  ab = (xb.z - xb.x) * (xb.w - xb.y);

    bool ok = true;
    if (lane < T_) {
        float4 tb = targets[b * T_ + lane];
        float4 xt = to_xyxy(tb);
        float  at = (xt.z - xt.x) * (xt.w - xt.y);
        float  g  = giou_precise(xb, ab, xt, at);
        ok = ((-g) > -0.1f);
    }
    bool all_ok = __all_sync(0xffffffffu, ok);

    if (lane == 0) {
        bool m = keep_prob && all_ok;
        g_mask[w]  = m ? 1 : 0;
        g_label[w] = (short)bi;
        if (write_mask) out[CSZ + w] = m ? 1.0f : 0.0f;
    }
}

// ---------------------------------------------------------------------------
// K2: single-pass cost tile. Block = 8 rows of batch b, 256 threads.
//   Stage: local mask-scan compaction (smem atomics only; value-order-free),
//          coalesced logits rows -> smem.
//   Compute: warp w owns row i0+w; lanes stride the valid list. All operand
//            traffic from registers/smem/L1; no runtime division.
//   Output: smem tile streamed once to global (coalesced float4).
// ---------------------------------------------------------------------------
__global__ __launch_bounds__(256) void cost_kernel(
    const float*  __restrict__ logits,       // current pred logits [B,Q,C]
    const float4* __restrict__ boxes,        // current pred boxes
    const float4* __restrict__ boxes_base,   // pseudo-target boxes
    float* __restrict__ out)
{
    __shared__ float sval[ROWS_PER_BLK * Q_];       // 28.8 KB
    __shared__ int   s_jl[Q_];                      // 3.6 KB (j | lab<<16)
    __shared__ float s_lg[ROWS_PER_BLK][C_ + 1];    // 2.9 KB (pad: stride 92)
    __shared__ int   s_n;

    int b  = blockIdx.y;
    int i0 = blockIdx.x * ROWS_PER_BLK;
    int t  = threadIdx.x;
    int nrows = min(ROWS_PER_BLK, Q_ - i0);

    if (t == 0) s_n = 0;

    // smem fill with 1e9
    float4* sval4 = (float4*)sval;
    const float4 F = make_float4(1e9f, 1e9f, 1e9f, 1e9f);
    #pragma unroll
    for (int k = 0; k < (ROWS_PER_BLK * NR4 + 255) / 256; ++k) {
        int idx = k * 256 + t;
        if (idx < ROWS_PER_BLK * NR4) sval4[idx] = F;
    }

    // coalesced stage of this block's logits rows
    for (int idx = t; idx < nrows * C_; idx += 256) {
        int ii = idx / C_;               // compile-time divisor
        int c  = idx - ii * C_;
        s_lg[ii][c] = logits[(size_t)(b * Q_ + i0 + ii) * C_ + c];
    }
    __syncthreads();   // s_n=0 visible before compaction atomics

    // local mask scan + compaction (order does not affect output values)
    if (t < NR4) {
        uchar4 m4 = ((const uchar4*)(g_mask + b * Q_))[t];
        unsigned char mb[4] = {m4.x, m4.y, m4.z, m4.w};
        #pragma unroll
        for (int k = 0; k < 4; ++k) {
            if (mb[k]) {
                int j = 4 * t + k;
                int slot = atomicAdd(&s_n, 1);
                s_jl[slot] = j | ((int)g_label[b * Q_ + j] << 16);
            }
        }
    }
    __syncthreads();
    int n = s_n;

    // warp-per-row compute
    int w = t >> 5, lane = t & 31;
    if (w < nrows) {
        int i = i0 + w;
        float4 bi = boxes[b * Q_ + i];           // broadcast across warp
        float4 xi = to_xyxy(bi);
        float  ai = (xi.z - xi.x) * (xi.w - xi.y);

        for (int v = lane; v < n; v += 32) {
            int jl  = s_jl[v];
            int j   = jl & 0xFFFF;
            int lab = jl >> 16;

            float4 bj = boxes_base[b * Q_ + j];  // L1-resident after first warp
            float4 xj = to_xyxy(bj);
            float  aj = (xj.z - xj.x) * (xj.w - xj.y);

            float x   = s_lg[w][lab];
            float p   = fast_rcp(1.0f + fast_exp(-x));
            float omp = 1.0f - p;
            float pos = 0.25f * omp * omp * (-fast_log(p   + 1e-8f));
            float neg = 0.75f * p   * p   * (-fast_log(omp + 1e-8f));
            float cls = 2.0f * (pos - neg);

            float l1 = fabsf(bi.x - bj.x) + fabsf(bi.y - bj.y)
                     + fabsf(bi.z - bj.z) + fabsf(bi.w - bj.w);
            float g  = giou_fast(xi, ai, xj, aj);

            sval[w * Q_ + j] = fmaf(5.0f, l1, cls) - 2.0f * g;
        }
    }
    __syncthreads();

    // single coalesced pass to global
    float4* out4 = (float4*)out;
    size_t  obase4 = ((size_t)b * Q_ + i0) * NR4;
    for (int idx = t; idx < nrows * NR4; idx += 256)
        out4[obase4 + idx] = sval4[idx];
}

// ---------------------------------------------------------------------------
extern "C" void kernel_launch(void* const* d_in, const int* in_sizes, int n_in,
                              void* d_out, int out_size)
{
    const float*  pred_logits      = (const float*) d_in[0];
    const float4* pred_boxes       = (const float4*)d_in[1];
    const float*  pred_logits_base = (const float*) d_in[2];
    const float4* pred_boxes_base  = (const float4*)d_in[3];
    const float4* targets_boxes    = (const float4*)d_in[4];
    float* out = (float*)d_out;

    int write_mask = (out_size >= (int)(CSZ + BQ)) ? 1 : 0;

    pseudo_kernel<<<BQ / 8, 256>>>(pred_logits_base, pred_boxes_base,
                                   targets_boxes, out, write_mask);

    dim3 grid(BLKS_PER_BATCH, B_);   // (113, 32)
    cost_kernel<<<grid, 256>>>(pred_logits, pred_boxes, pred_boxes_base, out);
}

// round 9
// speedup vs baseline: 1.1808x; 1.0678x over previous
#include <cuda_runtime.h>
#include <cstdint>

// Shapes fixed by the problem
#define B_  32
#define Q_  900
#define C_  91
#define T_  30
#define BQ  (B_ * Q_)                 // 28800
#define CSZ ((size_t)B_ * Q_ * Q_)    // 25,920,000
#define NR4 (Q_ / 4)                  // 225 float4 per row
#define ROWS_PER_BLK 8
#define BLKS_PER_BATCH ((Q_ + ROWS_PER_BLK - 1) / ROWS_PER_BLK)   // 113

// Scratch (device globals — fully rewritten every launch; no allocation)
__device__ unsigned char g_mask[BQ];
__device__ short         g_label[BQ];

// ---------------------------------------------------------------------------
// FMA-pipe math (no MUFU) for cost values; filter path stays IEEE-precise.
// ---------------------------------------------------------------------------
__device__ __forceinline__ float fast_rcp(float x) {
    float y = __int_as_float(0x7EF311C3 - __float_as_int(x));
    y = y * fmaf(-x, y, 2.0f);
    y = y * fmaf(-x, y, 2.0f);
    return y;
}

__device__ __forceinline__ float fast_exp(float x) {
    float y = fminf(fmaxf(x * 1.4426950408889634f, -120.0f), 120.0f);
    float n = rintf(y);
    float f = y - n;
    float p = 1.3333558146e-3f;
    p = fmaf(p, f, 9.6180905e-3f);
    p = fmaf(p, f, 5.550410866e-2f);
    p = fmaf(p, f, 2.402265069e-1f);
    p = fmaf(p, f, 6.931471806e-1f);
    p = fmaf(p, f, 1.0f);
    return __int_as_float(__float_as_int(p) + (((int)n) << 23));
}

__device__ __forceinline__ float fast_log(float x) {
    int   xi = __float_as_int(x);
    int   e  = (xi >> 23) - 127;
    float m  = __int_as_float((xi & 0x007FFFFF) | 0x3F800000);  // [1,2)
    bool  c  = m > 1.41421356f;
    m = c ? 0.5f * m : m;
    e = c ? e + 1 : e;
    float f = m - 1.0f;
    float w = f * f;
    float p = 7.0376836292e-2f;
    p = fmaf(p, f, -1.1514610310e-1f);
    p = fmaf(p, f,  1.1676998740e-1f);
    p = fmaf(p, f, -1.2420140846e-1f);
    p = fmaf(p, f,  1.4249322787e-1f);
    p = fmaf(p, f, -1.6668057665e-1f);
    p = fmaf(p, f,  2.0000714765e-1f);
    p = fmaf(p, f, -2.4999993993e-1f);
    p = fmaf(p, f,  3.3333331174e-1f);
    float y = f * w * p - 0.5f * w;
    return fmaf((float)e, 0.69314718056f, f + y);
}

__device__ __forceinline__ float4 to_xyxy(float4 b) {
    float hw = 0.5f * b.z, hh = 0.5f * b.w;
    return make_float4(b.x - hw, b.y - hh, b.x + hw, b.y + hh);
}

// Precise GIoU (IEEE div) — only for the boundary-sensitive filter compare.
__device__ __forceinline__ float giou_precise(float4 xa, float aa, float4 xb, float ab) {
    float w = fmaxf(fminf(xa.z, xb.z) - fmaxf(xa.x, xb.x), 0.0f);
    float h = fmaxf(fminf(xa.w, xb.w) - fmaxf(xa.y, xb.y), 0.0f);
    float inter = w * h;
    float uni = aa + ab - inter;
    float wc = fmaxf(fmaxf(xa.z, xb.z) - fminf(xa.x, xb.x), 0.0f);
    float hc = fmaxf(fmaxf(xa.w, xb.w) - fminf(xa.y, xb.y), 0.0f);
    float ac = wc * hc;
    return inter / uni - (ac - uni) / ac;
}

// Fast GIoU for cost values: one fused Newton reciprocal.
__device__ __forceinline__ float giou_fast(float4 xa, float aa, float4 xb, float ab) {
    float w = fmaxf(fminf(xa.z, xb.z) - fmaxf(xa.x, xb.x), 0.0f);
    float h = fmaxf(fminf(xa.w, xb.w) - fmaxf(xa.y, xb.y), 0.0f);
    float inter = w * h;
    float uni = aa + ab - inter;
    float wc = fmaxf(xa.z, xb.z) - fminf(xa.x, xb.x);
    float hc = fmaxf(xa.w, xb.w) - fminf(xa.y, xb.y);
    float ac = wc * hc;
    float num = inter * ac - (ac - uni) * uni;
    return num * fast_rcp(uni * ac);
}

__device__ __forceinline__ unsigned ordkey(float v) {
    unsigned u = __float_as_uint(v);
    return ((int)u >= 0) ? (u | 0x80000000u) : ~u;
}

__device__ __forceinline__ uint32_t smem_u32(const void* p) {
    uint32_t a;
    asm("{ .reg .u64 t; cvta.to.shared.u64 t, %1; cvt.u32.u64 %0, t; }"
        : "=r"(a) : "l"(p));
    return a;
}

// ---------------------------------------------------------------------------
// K1: pseudo-label generation. One warp per (b, j). Plain stores, no atomics.
// ---------------------------------------------------------------------------
__global__ __launch_bounds__(256) void pseudo_kernel(
    const float*  __restrict__ logits_base,
    const float4* __restrict__ boxes_base,
    const float4* __restrict__ targets,
    float* __restrict__ out, int write_mask)
{
    int w    = (blockIdx.x * 256 + threadIdx.x) >> 5;   // exactly covers BQ
    int lane = threadIdx.x & 31;
    int b    = w / Q_;

    const float* lg = logits_base + (size_t)w * C_;
    float v0 = lg[lane];
    float v1 = lg[lane + 32];
    float v2 = (lane + 64 < C_) ? lg[lane + 64] : -3.4e38f;
    unsigned k0 = ordkey(v0), k1 = ordkey(v1), k2 = ordkey(v2);
    unsigned best = __reduce_max_sync(0xffffffffu, max(k0, max(k1, k2)));

    int bi;
    unsigned m0 = __ballot_sync(0xffffffffu, k0 == best);
    unsigned m1 = __ballot_sync(0xffffffffu, k1 == best);
    unsigned m2 = __ballot_sync(0xffffffffu, k2 == best);
    if (m0)      bi = __ffs(m0) - 1;
    else if (m1) bi = 32 + __ffs(m1) - 1;
    else         bi = 64 + __ffs(m2) - 1;

    bool keep_prob = best > 0x80000000u;   // max logit > 0 <=> sigmoid > 0.5

    float4 bb = boxes_base[w];
    float4 xb = to_xyxy(bb);
    float  ab = (xb.z - xb.x) * (xb.w - xb.y);

    bool ok = true;
    if (lane < T_) {
        float4 tb = targets[b * T_ + lane];
        float4 xt = to_xyxy(tb);
        float  at = (xt.z - xt.x) * (xt.w - xt.y);
        float  g  = giou_precise(xb, ab, xt, at);
        ok = ((-g) > -0.1f);
    }
    bool all_ok = __all_sync(0xffffffffu, ok);

    if (lane == 0) {
        bool m = keep_prob && all_ok;
        g_mask[w]  = m ? 1 : 0;
        g_label[w] = (short)bi;
        if (write_mask) out[CSZ + w] = m ? 1.0f : 0.0f;
    }
}

// ---------------------------------------------------------------------------
// K2: single-pass cost tile. Block = 8 rows of batch b, 256 threads.
//   - warp-aggregated compaction of the batch's mask (1 atomic per warp)
//   - warp-per-row compute into the smem tile
//   - ONE cp.async.bulk store smem -> global (no per-element LDS/STG)
// ---------------------------------------------------------------------------
__global__ __launch_bounds__(256) void cost_kernel(
    const float*  __restrict__ logits,       // current pred logits [B,Q,C]
    const float4* __restrict__ boxes,        // current pred boxes
    const float4* __restrict__ boxes_base,   // pseudo-target boxes
    float* __restrict__ out)
{
    __shared__ float sval[ROWS_PER_BLK * Q_];       // 28.8 KB
    __shared__ int   s_jl[Q_];                      // 3.6 KB (j | lab<<16)
    __shared__ float s_lg[ROWS_PER_BLK][C_ + 1];    // 2.9 KB
    __shared__ int   s_n;

    int b  = blockIdx.y;
    int i0 = blockIdx.x * ROWS_PER_BLK;
    int t  = threadIdx.x;
    int lane = t & 31, w = t >> 5;
    int nrows = min(ROWS_PER_BLK, Q_ - i0);

    if (t == 0) s_n = 0;

    // smem fill with 1e9
    float4* sval4 = (float4*)sval;
    const float4 F = make_float4(1e9f, 1e9f, 1e9f, 1e9f);
    #pragma unroll
    for (int k = 0; k < (ROWS_PER_BLK * NR4 + 255) / 256; ++k) {
        int idx = k * 256 + t;
        if (idx < ROWS_PER_BLK * NR4) sval4[idx] = F;
    }

    // coalesced stage of this block's logits rows
    for (int idx = t; idx < nrows * C_; idx += 256) {
        int ii = idx / C_;
        int c  = idx - ii * C_;
        s_lg[ii][c] = logits[(size_t)(b * Q_ + i0 + ii) * C_ + c];
    }
    __syncthreads();   // s_n=0 visible before compaction atomics

    // warp-aggregated mask compaction (order-free; 1 atomic per warp)
    {
        int js[4]; int cnt = 0;
        if (t < NR4) {
            uchar4 m4 = ((const uchar4*)(g_mask + b * Q_))[t];
            if (m4.x) js[cnt++] = 4 * t + 0;
            if (m4.y) js[cnt++] = 4 * t + 1;
            if (m4.z) js[cnt++] = 4 * t + 2;
            if (m4.w) js[cnt++] = 4 * t + 3;
        }
        int incl = cnt;
        #pragma unroll
        for (int off = 1; off < 32; off <<= 1) {
            int v = __shfl_up_sync(0xffffffffu, incl, off);
            if (lane >= off) incl += v;
        }
        int wtot = __shfl_sync(0xffffffffu, incl, 31);
        int base = 0;
        if (lane == 31 && wtot) base = atomicAdd(&s_n, wtot);
        base = __shfl_sync(0xffffffffu, base, 31);
        int o = base + incl - cnt;
        for (int k = 0; k < cnt; ++k) {
            int j = js[k];
            s_jl[o + k] = j | ((int)g_label[b * Q_ + j] << 16);
        }
    }
    __syncthreads();
    int n = s_n;

    // warp-per-row compute
    if (w < nrows) {
        int i = i0 + w;
        float4 bi = boxes[b * Q_ + i];           // broadcast across warp
        float4 xi = to_xyxy(bi);
        float  ai = (xi.z - xi.x) * (xi.w - xi.y);

        for (int v = lane; v < n; v += 32) {
            int jl  = s_jl[v];
            int j   = jl & 0xFFFF;
            int lab = jl >> 16;

            float4 bj = boxes_base[b * Q_ + j];
            float4 xj = to_xyxy(bj);
            float  aj = (xj.z - xj.x) * (xj.w - xj.y);

            float x   = s_lg[w][lab];
            float p   = fast_rcp(1.0f + fast_exp(-x));
            float omp = 1.0f - p;
            float pos = 0.25f * omp * omp * (-fast_log(p   + 1e-8f));
            float neg = 0.75f * p   * p   * (-fast_log(omp + 1e-8f));
            float cls = 2.0f * (pos - neg);

            float l1 = fabsf(bi.x - bj.x) + fabsf(bi.y - bj.y)
                     + fabsf(bi.z - bj.z) + fabsf(bi.w - bj.w);
            float g  = giou_fast(xi, ai, xj, aj);

            sval[w * Q_ + j] = fmaf(5.0f, l1, cls) - 2.0f * g;
        }
    }
    __syncthreads();

    // make generic-proxy smem writes visible to the async (bulk-copy) proxy
    asm volatile("fence.proxy.async.shared::cta;" ::: "memory");

    // ONE bulk store: smem tile -> global (async engine, no LSU wavefronts)
    if (t == 0) {
        float*   gdst  = out + ((size_t)b * Q_ + i0) * Q_;
        uint32_t ssrc  = smem_u32(sval);
        uint32_t bytes = (uint32_t)(nrows * Q_ * sizeof(float));   // mult of 16
        asm volatile(
            "cp.async.bulk.global.shared::cta.bulk_group [%0], [%1], %2;"
            :: "l"(gdst), "r"(ssrc), "r"(bytes) : "memory");
        asm volatile("cp.async.bulk.commit_group;" ::: "memory");
        asm volatile("cp.async.bulk.wait_group 0;" ::: "memory");
    }
    __syncthreads();   // smem must stay live until the bulk store completes
}

// ---------------------------------------------------------------------------
extern "C" void kernel_launch(void* const* d_in, const int* in_sizes, int n_in,
                              void* d_out, int out_size)
{
    const float*  pred_logits      = (const float*) d_in[0];
    const float4* pred_boxes       = (const float4*)d_in[1];
    const float*  pred_logits_base = (const float*) d_in[2];
    const float4* pred_boxes_base  = (const float4*)d_in[3];
    const float4* targets_boxes    = (const float4*)d_in[4];
    float* out = (float*)d_out;

    int write_mask = (out_size >= (int)(CSZ + BQ)) ? 1 : 0;

    pseudo_kernel<<<BQ / 8, 256>>>(pred_logits_base, pred_boxes_base,
                                   targets_boxes, out, write_mask);

    dim3 grid(BLKS_PER_BATCH, B_);   // (113, 32)
    cost_kernel<<<grid, 256>>>(pred_logits, pred_boxes, pred_boxes_base, out);
}

// round 10
// speedup vs baseline: 1.2175x; 1.0311x over previous
#include <cuda_runtime.h>
#include <cstdint>

// Shapes fixed by the problem
#define B_  32
#define Q_  900
#define C_  91
#define T_  30
#define BQ  (B_ * Q_)                 // 28800
#define CSZ ((size_t)B_ * Q_ * Q_)    // 25,920,000
#define NR4 (Q_ / 4)                  // 225 float4 per row
#define ROWS_PER_BLK 8
#define BLKS_PER_BATCH ((Q_ + ROWS_PER_BLK - 1) / ROWS_PER_BLK)   // 113

// Scratch (device globals — zero-init at load; counters self-reset each launch)
__device__ int    g_cnt[B_];      // valid count per batch
__device__ int    g_done[B_];     // completion ticket per batch
__device__ int    g_jl[BQ];       // compacted: j | lab<<16   (stride Q_ per batch)
__device__ float4 g_bj4[BQ];      // compacted: cxcywh box

// ---------------------------------------------------------------------------
__device__ __forceinline__ float fast_rcp(float x) {
    float y = __int_as_float(0x7EF311C3 - __float_as_int(x));
    y = y * fmaf(-x, y, 2.0f);
    y = y * fmaf(-x, y, 2.0f);
    return y;
}

__device__ __forceinline__ float fast_exp(float x) {
    float y = fminf(fmaxf(x * 1.4426950408889634f, -120.0f), 120.0f);
    float n = rintf(y);
    float f = y - n;
    float p = 1.3333558146e-3f;
    p = fmaf(p, f, 9.6180905e-3f);
    p = fmaf(p, f, 5.550410866e-2f);
    p = fmaf(p, f, 2.402265069e-1f);
    p = fmaf(p, f, 6.931471806e-1f);
    p = fmaf(p, f, 1.0f);
    return __int_as_float(__float_as_int(p) + (((int)n) << 23));
}

__device__ __forceinline__ float4 to_xyxy(float4 b) {
    float hw = 0.5f * b.z, hh = 0.5f * b.w;
    return make_float4(b.x - hw, b.y - hh, b.x + hw, b.y + hh);
}

// Precise GIoU (IEEE div) — only for the boundary-sensitive filter compare.
__device__ __forceinline__ float giou_precise(float4 xa, float aa, float4 xb, float ab) {
    float w = fmaxf(fminf(xa.z, xb.z) - fmaxf(xa.x, xb.x), 0.0f);
    float h = fmaxf(fminf(xa.w, xb.w) - fmaxf(xa.y, xb.y), 0.0f);
    float inter = w * h;
    float uni = aa + ab - inter;
    float wc = fmaxf(fmaxf(xa.z, xb.z) - fminf(xa.x, xb.x), 0.0f);
    float hc = fmaxf(fmaxf(xa.w, xb.w) - fminf(xa.y, xb.y), 0.0f);
    float ac = wc * hc;
    return inter / uni - (ac - uni) / ac;
}

// Fast GIoU for cost values: one fused Newton reciprocal.
__device__ __forceinline__ float giou_fast(float4 xa, float aa, float4 xb, float ab) {
    float w = fmaxf(fminf(xa.z, xb.z) - fmaxf(xa.x, xb.x), 0.0f);
    float h = fmaxf(fminf(xa.w, xb.w) - fmaxf(xa.y, xb.y), 0.0f);
    float inter = w * h;
    float uni = aa + ab - inter;
    float wc = fmaxf(xa.z, xb.z) - fminf(xa.x, xb.x);
    float hc = fmaxf(xa.w, xb.w) - fminf(xa.y, xb.y);
    float ac = wc * hc;
    float num = inter * ac - (ac - uni) * uni;
    return num * fast_rcp(uni * ac);
}

__device__ __forceinline__ unsigned ordkey(float v) {
    unsigned u = __float_as_uint(v);
    return ((int)u >= 0) ? (u | 0x80000000u) : ~u;
}

__device__ __forceinline__ uint32_t smem_u32(const void* p) {
    uint32_t a;
    asm("{ .reg .u64 t; cvta.to.shared.u64 t, %1; cvt.u32.u64 %0, t; }"
        : "=r"(a) : "l"(p));
    return a;
}

// ---------------------------------------------------------------------------
// K1: pseudo-label generation + GLOBAL compaction. One warp per (b, j).
// ---------------------------------------------------------------------------
__global__ __launch_bounds__(256) void pseudo_kernel(
    const float*  __restrict__ logits_base,
    const float4* __restrict__ boxes_base,
    const float4* __restrict__ targets,
    float* __restrict__ out, int write_mask)
{
    int w    = (blockIdx.x * 256 + threadIdx.x) >> 5;   // exactly covers BQ
    int lane = threadIdx.x & 31;
    int b    = w / Q_;

    const float* lg = logits_base + (size_t)w * C_;
    float v0 = lg[lane];
    float v1 = lg[lane + 32];
    float v2 = (lane + 64 < C_) ? lg[lane + 64] : -3.4e38f;
    unsigned k0 = ordkey(v0), k1 = ordkey(v1), k2 = ordkey(v2);
    unsigned best = __reduce_max_sync(0xffffffffu, max(k0, max(k1, k2)));

    int bi;
    unsigned m0 = __ballot_sync(0xffffffffu, k0 == best);
    unsigned m1 = __ballot_sync(0xffffffffu, k1 == best);
    unsigned m2 = __ballot_sync(0xffffffffu, k2 == best);
    if (m0)      bi = __ffs(m0) - 1;
    else if (m1) bi = 32 + __ffs(m1) - 1;
    else         bi = 64 + __ffs(m2) - 1;

    bool keep_prob = best > 0x80000000u;   // max logit > 0 <=> sigmoid > 0.5

    float4 bb = boxes_base[w];
    float4 xb = to_xyxy(bb);
    float  ab = (xb.z - xb.x) * (xb.w - xb.y);

    bool ok = true;
    if (lane < T_) {
        float4 tb = targets[b * T_ + lane];
        float4 xt = to_xyxy(tb);
        float  at = (xt.z - xt.x) * (xt.w - xt.y);
        float  g  = giou_precise(xb, ab, xt, at);
        ok = ((-g) > -0.1f);
    }
    bool all_ok = __all_sync(0xffffffffu, ok);

    if (lane == 0) {
        bool m = keep_prob && all_ok;
        if (write_mask) out[CSZ + w] = m ? 1.0f : 0.0f;
        if (m) {
            int slot = atomicAdd(&g_cnt[b], 1);         // order-free: each slot
            g_jl[b * Q_ + slot]  = (w - b * Q_) | (bi << 16);  // fully describes
            g_bj4[b * Q_ + slot] = bb;                          // its column
        }
    }
}

// ---------------------------------------------------------------------------
// K2: single-pass cost tile. Block = 8 rows of batch b, 256 threads.
//   No compaction here: lanes read the COMPACTED arrays at consecutive
//   addresses (coalesced, L1-resident). Warp w owns row i0+w.
//   One cp.async.bulk store smem -> global. Ticket tail resets counters.
// ---------------------------------------------------------------------------
__global__ __launch_bounds__(256) void cost_kernel(
    const float*  __restrict__ logits,       // current pred logits [B,Q,C]
    const float4* __restrict__ boxes,        // current pred boxes
    float* __restrict__ out)
{
    __shared__ float sval[ROWS_PER_BLK * Q_];       // 28.8 KB
    __shared__ float s_lg[ROWS_PER_BLK][C_ + 1];    // 2.9 KB

    int b  = blockIdx.y;
    int i0 = blockIdx.x * ROWS_PER_BLK;
    int t  = threadIdx.x;
    int lane = t & 31, w = t >> 5;
    int nrows = min(ROWS_PER_BLK, Q_ - i0);
    int n = g_cnt[b];                                // uniform per block

    // smem fill with 1e9
    float4* sval4 = (float4*)sval;
    const float4 F = make_float4(1e9f, 1e9f, 1e9f, 1e9f);
    #pragma unroll
    for (int k = 0; k < (ROWS_PER_BLK * NR4 + 255) / 256; ++k) {
        int idx = k * 256 + t;
        if (idx < ROWS_PER_BLK * NR4) sval4[idx] = F;
    }

    // coalesced stage of this block's logits rows
    for (int idx = t; idx < nrows * C_; idx += 256) {
        int ii = idx / C_;
        int c  = idx - ii * C_;
        s_lg[ii][c] = logits[(size_t)(b * Q_ + i0 + ii) * C_ + c];
    }
    __syncthreads();

    // warp-per-row compute over the compacted valid list
    if (w < nrows) {
        int i = i0 + w;
        float4 bi = boxes[b * Q_ + i];        // warp-broadcast
        float4 xi = to_xyxy(bi);
        float  ai = bi.z * bi.w;              // area in cxcywh = w*h

        const int*    jlp = g_jl  + b * Q_;
        const float4* bjp = g_bj4 + b * Q_;

        for (int v = lane; v < n; v += 32) {
            int jl  = jlp[v];                 // coalesced
            int j   = jl & 0xFFFF;
            int lab = jl >> 16;

            float4 bj = bjp[v];               // coalesced
            float4 xj = to_xyxy(bj);
            float  aj = bj.z * bj.w;

            // focal class cost via softplus identity (1 exp, 1 rcp, 1 log1p)
            float x = s_lg[w][lab];
            float a = fabsf(x);
            float e = fast_exp(-a);
            float r = fast_rcp(1.0f + e);
            float u = e * fast_rcp(2.0f + e);           // atanh-based log1p
            float l = u * fmaf(0.66666667f, u * u, 2.0f);
            float p   = (x >= 0.0f) ? r : e * r;
            float omp = (x >= 0.0f) ? e * r : r;
            float mlogp   = fmaxf(-x, 0.0f) + l;        // -log(p)
            float mlogomp = fmaxf( x, 0.0f) + l;        // -log(1-p)
            float cls = 0.5f * omp * omp * mlogp - 1.5f * p * p * mlogomp;

            float l1 = fabsf(bi.x - bj.x) + fabsf(bi.y - bj.y)
                     + fabsf(bi.z - bj.z) + fabsf(bi.w - bj.w);
            float g  = giou_fast(xi, ai, xj, aj);

            sval[w * Q_ + j] = fmaf(5.0f, l1, cls) - 2.0f * g;
        }
    }
    __syncthreads();

    // make generic-proxy smem writes visible to the async (bulk-copy) proxy
    asm volatile("fence.proxy.async.shared::cta;" ::: "memory");

    // ONE bulk store: smem tile -> global
    if (t == 0) {
        float*   gdst  = out + ((size_t)b * Q_ + i0) * Q_;
        uint32_t ssrc  = smem_u32(sval);
        uint32_t bytes = (uint32_t)(nrows * Q_ * sizeof(float));   // mult of 16
        asm volatile(
            "cp.async.bulk.global.shared::cta.bulk_group [%0], [%1], %2;"
            :: "l"(gdst), "r"(ssrc), "r"(bytes) : "memory");
        asm volatile("cp.async.bulk.commit_group;" ::: "memory");
        asm volatile("cp.async.bulk.wait_group 0;" ::: "memory");
    }
    __syncthreads();   // smem must stay live until the bulk store completes

    // ticket tail: last block of this batch resets counters for next replay
    __threadfence();
    if (t == 0) {
        int d = atomicAdd(&g_done[b], 1);
        if (d == BLKS_PER_BATCH - 1) {
            g_cnt[b]  = 0;
            g_done[b] = 0;
        }
    }
}

// ---------------------------------------------------------------------------
extern "C" void kernel_launch(void* const* d_in, const int* in_sizes, int n_in,
                              void* d_out, int out_size)
{
    const float*  pred_logits      = (const float*) d_in[0];
    const float4* pred_boxes       = (const float4*)d_in[1];
    const float*  pred_logits_base = (const float*) d_in[2];
    const float4* pred_boxes_base  = (const float4*)d_in[3];
    const float4* targets_boxes    = (const float4*)d_in[4];
    float* out = (float*)d_out;

    int write_mask = (out_size >= (int)(CSZ + BQ)) ? 1 : 0;

    pseudo_kernel<<<BQ / 8, 256>>>(pred_logits_base, pred_boxes_base,
                                   targets_boxes, out, write_mask);

    dim3 grid(BLKS_PER_BATCH, B_);   // (113, 32)
    cost_kernel<<<grid, 256>>>(pred_logits, pred_boxes, out);
}

// round 12
// speedup vs baseline: 1.2697x; 1.0428x over previous
#include <cuda_runtime.h>
#include <cstdint>

// Shapes fixed by the problem
#define B_  32
#define Q_  900
#define C_  91
#define T_  30
#define BQ  (B_ * Q_)                 // 28800
#define CSZ ((size_t)B_ * Q_ * Q_)    // 25,920,000
#define NR4 (Q_ / 4)                  // 225 float4 per row
#define ROWS_PER_BLK 16
#define THREADS_K2 512
#define BLKS_PER_BATCH ((Q_ + ROWS_PER_BLK - 1) / ROWS_PER_BLK)   // 57
#define NCHUNK 128

// Dynamic smem layout (bytes):
//   [0, SVAL_B)              float  sval[ROWS_PER_BLK * Q_]      57600
//   [SVAL_B, +SBJ_B)         float4 s_bj[NCHUNK]                  2048
//   [.., +SLG_B)             float  s_lg[ROWS_PER_BLK][C_+1]      5888
//   [.., +SPK_B)             int    s_pk[NCHUNK]                   512
#define SVAL_B (ROWS_PER_BLK * Q_ * 4)
#define SBJ_B  (NCHUNK * 16)
#define SLG_B  (ROWS_PER_BLK * (C_ + 1) * 4)
#define SPK_B  (NCHUNK * 4)
#define SMEM_K2 (SVAL_B + SBJ_B + SLG_B + SPK_B)     // 66048

// Scratch (device globals — zero-init at load; counters self-reset each launch)
__device__ int    g_cnt[B_];      // valid count per batch
__device__ int    g_done[B_];     // completion ticket per batch
__device__ int    g_jl[BQ];       // compacted: j | lab<<16   (stride Q_ per batch)
__device__ float4 g_bj4[BQ];      // compacted: cxcywh box

// ---------------------------------------------------------------------------
__device__ __forceinline__ float fast_rcp(float x) {
    float y = __int_as_float(0x7EF311C3 - __float_as_int(x));
    y = y * fmaf(-x, y, 2.0f);
    y = y * fmaf(-x, y, 2.0f);
    return y;
}

__device__ __forceinline__ float fast_exp(float x) {
    float y = fminf(fmaxf(x * 1.4426950408889634f, -120.0f), 120.0f);
    float n = rintf(y);
    float f = y - n;
    float p = 1.3333558146e-3f;
    p = fmaf(p, f, 9.6180905e-3f);
    p = fmaf(p, f, 5.550410866e-2f);
    p = fmaf(p, f, 2.402265069e-1f);
    p = fmaf(p, f, 6.931471806e-1f);
    p = fmaf(p, f, 1.0f);
    return __int_as_float(__float_as_int(p) + (((int)n) << 23));
}

__device__ __forceinline__ float4 to_xyxy(float4 b) {
    float hw = 0.5f * b.z, hh = 0.5f * b.w;
    return make_float4(b.x - hw, b.y - hh, b.x + hw, b.y + hh);
}

// Precise GIoU (IEEE div) — only for the boundary-sensitive filter compare.
__device__ __forceinline__ float giou_precise(float4 xa, float aa, float4 xb, float ab) {
    float w = fmaxf(fminf(xa.z, xb.z) - fmaxf(xa.x, xb.x), 0.0f);
    float h = fmaxf(fminf(xa.w, xb.w) - fmaxf(xa.y, xb.y), 0.0f);
    float inter = w * h;
    float uni = aa + ab - inter;
    float wc = fmaxf(fmaxf(xa.z, xb.z) - fminf(xa.x, xb.x), 0.0f);
    float hc = fmaxf(fmaxf(xa.w, xb.w) - fminf(xa.y, xb.y), 0.0f);
    float ac = wc * hc;
    return inter / uni - (ac - uni) / ac;
}

// Fast GIoU for cost values: one fused Newton reciprocal.
__device__ __forceinline__ float giou_fast(float4 xa, float aa, float4 xb, float ab) {
    float w = fmaxf(fminf(xa.z, xb.z) - fmaxf(xa.x, xb.x), 0.0f);
    float h = fmaxf(fminf(xa.w, xb.w) - fmaxf(xa.y, xb.y), 0.0f);
    float inter = w * h;
    float uni = aa + ab - inter;
    float wc = fmaxf(xa.z, xb.z) - fminf(xa.x, xb.x);
    float hc = fmaxf(xa.w, xb.w) - fminf(xa.y, xb.y);
    float ac = wc * hc;
    float num = inter * ac - (ac - uni) * uni;
    return num * fast_rcp(uni * ac);
}

__device__ __forceinline__ unsigned ordkey(float v) {
    unsigned u = __float_as_uint(v);
    return ((int)u >= 0) ? (u | 0x80000000u) : ~u;
}

__device__ __forceinline__ uint32_t smem_u32(const void* p) {
    uint32_t a;
    asm("{ .reg .u64 t; cvta.to.shared.u64 t, %1; cvt.u32.u64 %0, t; }"
        : "=r"(a) : "l"(p));
    return a;
}

// ---------------------------------------------------------------------------
// K1: pseudo-label generation + GLOBAL compaction. One warp per (b, j).
// ---------------------------------------------------------------------------
__global__ __launch_bounds__(256) void pseudo_kernel(
    const float*  __restrict__ logits_base,
    const float4* __restrict__ boxes_base,
    const float4* __restrict__ targets,
    float* __restrict__ out, int write_mask)
{
    int w    = (blockIdx.x * 256 + threadIdx.x) >> 5;   // exactly covers BQ
    int lane = threadIdx.x & 31;
    int b    = w / Q_;

    const float* lg = logits_base + (size_t)w * C_;
    float v0 = lg[lane];
    float v1 = lg[lane + 32];
    float v2 = (lane + 64 < C_) ? lg[lane + 64] : -3.4e38f;
    unsigned k0 = ordkey(v0), k1 = ordkey(v1), k2 = ordkey(v2);
    unsigned best = __reduce_max_sync(0xffffffffu, max(k0, max(k1, k2)));

    int bi;
    unsigned m0 = __ballot_sync(0xffffffffu, k0 == best);
    unsigned m1 = __ballot_sync(0xffffffffu, k1 == best);
    unsigned m2 = __ballot_sync(0xffffffffu, k2 == best);
    if (m0)      bi = __ffs(m0) - 1;
    else if (m1) bi = 32 + __ffs(m1) - 1;
    else         bi = 64 + __ffs(m2) - 1;

    bool keep_prob = best > 0x80000000u;   // max logit > 0 <=> sigmoid > 0.5

    float4 bb = boxes_base[w];
    float4 xb = to_xyxy(bb);
    float  ab = (xb.z - xb.x) * (xb.w - xb.y);

    bool ok = true;
    if (lane < T_) {
        float4 tb = targets[b * T_ + lane];
        float4 xt = to_xyxy(tb);
        float  at = (xt.z - xt.x) * (xt.w - xt.y);
        float  g  = giou_precise(xb, ab, xt, at);
        ok = ((-g) > -0.1f);
    }
    bool all_ok = __all_sync(0xffffffffu, ok);

    if (lane == 0) {
        bool m = keep_prob && all_ok;
        if (write_mask) out[CSZ + w] = m ? 1.0f : 0.0f;
        if (m) {
            int slot = atomicAdd(&g_cnt[b], 1);
            g_jl[b * Q_ + slot]  = (w - b * Q_) | (bi << 16);
            g_bj4[b * Q_ + slot] = bb;
        }
    }
}

// ---------------------------------------------------------------------------
// K2: single-pass cost tile. Block = 16 rows of batch b, 512 threads.
//   Valid list staged into SMEM once per chunk (coalesced) -> inner loop is
//   LDS-only. Warp w owns row i0+w. One cp.async.bulk store smem -> global.
//   Dynamic smem (66 KB > 48 KB static cap).
// ---------------------------------------------------------------------------
__global__ __launch_bounds__(THREADS_K2) void cost_kernel(
    const float*  __restrict__ logits,       // current pred logits [B,Q,C]
    const float4* __restrict__ boxes,        // current pred boxes
    float* __restrict__ out)
{
    extern __shared__ char smem[];
    float*  sval  = (float*)smem;                         // [ROWS_PER_BLK * Q_]
    float4* s_bj  = (float4*)(smem + SVAL_B);             // [NCHUNK]
    float*  s_lgf = (float*)(smem + SVAL_B + SBJ_B);      // [ROWS_PER_BLK][C_+1]
    int*    s_pk  = (int*)(smem + SVAL_B + SBJ_B + SLG_B);// [NCHUNK]

    int b  = blockIdx.y;
    int i0 = blockIdx.x * ROWS_PER_BLK;
    int t  = threadIdx.x;
    int lane = t & 31, w = t >> 5;
    int nrows = min(ROWS_PER_BLK, Q_ - i0);
    int n = g_cnt[b];                                // uniform per block

    // smem fill with 1e9
    float4* sval4 = (float4*)sval;
    const float4 F = make_float4(1e9f, 1e9f, 1e9f, 1e9f);
    #pragma unroll
    for (int k = 0; k < (ROWS_PER_BLK * NR4 + THREADS_K2 - 1) / THREADS_K2; ++k) {
        int idx = k * THREADS_K2 + t;
        if (idx < ROWS_PER_BLK * NR4) sval4[idx] = F;
    }

    // coalesced stage of this block's logits rows
    for (int idx = t; idx < nrows * C_; idx += THREADS_K2) {
        int ii = idx / C_;
        int c  = idx - ii * C_;
        s_lgf[ii * (C_ + 1) + c] = logits[(size_t)(b * Q_ + i0 + ii) * C_ + c];
    }

    // per-warp row constants
    float4 bi, xi; float ai = 0.0f;
    if (w < nrows) {
        bi = boxes[b * Q_ + i0 + w];
        xi = to_xyxy(bi);
        ai = bi.z * bi.w;
    }

    const int*    jlp = g_jl  + b * Q_;
    const float4* bjp = g_bj4 + b * Q_;

    // chunked valid-list loop (single chunk when n <= NCHUNK, the usual case)
    for (int v0 = 0; ; v0 += NCHUNK) {
        int m = min(NCHUNK, n - v0);          // may be <= 0 when n == 0
        if (t < m) {
            s_pk[t] = jlp[v0 + t];            // coalesced
            s_bj[t] = bjp[v0 + t];            // coalesced
        }
        __syncthreads();                      // also covers fill + logits (1st iter)

        if (w < nrows) {
            for (int v = lane; v < m; v += 32) {
                int pk  = s_pk[v];
                int j   = pk & 0xFFFF;
                int lab = pk >> 16;

                float4 bj = s_bj[v];
                float4 xj = to_xyxy(bj);
                float  aj = bj.z * bj.w;

                // focal class cost via softplus identity
                float x = s_lgf[w * (C_ + 1) + lab];
                float a = fabsf(x);
                float e = fast_exp(-a);
                float r = fast_rcp(1.0f + e);
                float u = e * fast_rcp(2.0f + e);
                float l = u * fmaf(0.66666667f, u * u, 2.0f);   // log1p(e)
                float p   = (x >= 0.0f) ? r : e * r;
                float omp = (x >= 0.0f) ? e * r : r;
                float mlogp   = fmaxf(-x, 0.0f) + l;
                float mlogomp = fmaxf( x, 0.0f) + l;
                float cls = 0.5f * omp * omp * mlogp - 1.5f * p * p * mlogomp;

                float l1 = fabsf(bi.x - bj.x) + fabsf(bi.y - bj.y)
                         + fabsf(bi.z - bj.z) + fabsf(bi.w - bj.w);
                float g  = giou_fast(xi, ai, xj, aj);

                sval[w * Q_ + j] = fmaf(5.0f, l1, cls) - 2.0f * g;
            }
        }
        if (v0 + NCHUNK >= n) break;          // uniform exit
        __syncthreads();                      // drain before restaging s_pk/s_bj
    }
    __syncthreads();                          // compute visible block-wide

    // make generic-proxy smem writes visible to the async (bulk-copy) proxy
    asm volatile("fence.proxy.async.shared::cta;" ::: "memory");

    // ONE bulk store: smem tile -> global
    if (t == 0) {
        float*   gdst  = out + ((size_t)b * Q_ + i0) * Q_;
        uint32_t ssrc  = smem_u32(sval);
        uint32_t bytes = (uint32_t)(nrows * Q_ * sizeof(float));   // mult of 16
        asm volatile(
            "cp.async.bulk.global.shared::cta.bulk_group [%0], [%1], %2;"
            :: "l"(gdst), "r"(ssrc), "r"(bytes) : "memory");
        asm volatile("cp.async.bulk.commit_group;" ::: "memory");
        asm volatile("cp.async.bulk.wait_group 0;" ::: "memory");
    }
    __syncthreads();   // smem must stay live until the bulk store completes

    // ticket tail: last block of this batch resets counters for next replay
    __threadfence();
    if (t == 0) {
        int d = atomicAdd(&g_done[b], 1);
        if (d == BLKS_PER_BATCH - 1) {
            g_cnt[b]  = 0;
            g_done[b] = 0;
        }
    }
}

// ---------------------------------------------------------------------------
extern "C" void kernel_launch(void* const* d_in, const int* in_sizes, int n_in,
                              void* d_out, int out_size)
{
    const float*  pred_logits      = (const float*) d_in[0];
    const float4* pred_boxes       = (const float4*)d_in[1];
    const float*  pred_logits_base = (const float*) d_in[2];
    const float4* pred_boxes_base  = (const float4*)d_in[3];
    const float4* targets_boxes    = (const float4*)d_in[4];
    float* out = (float*)d_out;

    int write_mask = (out_size >= (int)(CSZ + BQ)) ? 1 : 0;

    static int smem_set = 0;
    if (!smem_set) {
        cudaFuncSetAttribute(cost_kernel,
                             cudaFuncAttributeMaxDynamicSharedMemorySize,
                             SMEM_K2);
        smem_set = 1;
    }

    pseudo_kernel<<<BQ / 8, 256>>>(pred_logits_base, pred_boxes_base,
                                   targets_boxes, out, write_mask);

    dim3 grid(BLKS_PER_BATCH, B_);   // (57, 32)
    cost_kernel<<<grid, THREADS_K2, SMEM_K2>>>(pred_logits, pred_boxes, out);
}